// round 13
// baseline (speedup 1.0000x reference)
#include <cuda_runtime.h>
#include <cuda_bf16.h>
#include <cuda_fp16.h>
#include <mma.h>
#include <math.h>
#include <stdint.h>

using namespace nvcuda;

#define BATCH 2
#define SEQ   2048
#define DM    1024
#define NH    16
#define HD    64
#define MTOT  (BATCH*SEQ)
#define JT    (SEQ/128)
#define KC    64
#define LDK   72
#define STG_LD 136

static const size_t OUT_ELEMS  = (size_t)BATCH * SEQ * DM;
static const size_t ATTN_ELEMS = (size_t)BATCH * NH * SEQ * SEQ;

// ---------------------------------------------------------------------------
// Device scratch
// ---------------------------------------------------------------------------
__device__ __nv_bfloat16 g_xq_hi[MTOT*DM], g_xq_lo[MTOT*DM];
__device__ __nv_bfloat16 g_xk_hi[MTOT*DM], g_xk_lo[MTOT*DM];
__device__ __nv_bfloat16 g_xv_hi[MTOT*DM], g_xv_lo[MTOT*DM];
__device__ __nv_bfloat16 g_wq_hi[DM*DM], g_wq_lo[DM*DM];
__device__ __nv_bfloat16 g_wk_hi[DM*DM], g_wk_lo[DM*DM];
__device__ __nv_bfloat16 g_wv_hi[DM*DM], g_wv_lo[DM*DM];
__device__ __nv_bfloat16 g_wo_hi[DM*DM], g_wo_lo[DM*DM];
__device__ __nv_bfloat16 g_q_hi[BATCH*NH*SEQ*HD], g_q_lo[BATCH*NH*SEQ*HD];
__device__ __nv_bfloat16 g_k_hi[BATCH*NH*SEQ*HD], g_k_lo[BATCH*NH*SEQ*HD];
__device__ __half        g_v_hi[BATCH*NH*SEQ*HD], g_v_lo[BATCH*NH*SEQ*HD];
__device__ __nv_bfloat16 g_ctx_hi[MTOT*DM], g_ctx_lo[MTOT*DM];
__device__ __half g_e[(size_t)BATCH*NH*SEQ*SEQ];
__device__ float g_attn_scratch[(size_t)BATCH*NH*SEQ*SEQ];

// ---------------------------------------------------------------------------
// Helpers
// ---------------------------------------------------------------------------
__device__ __forceinline__ void cp16(void* dst, const void* src) {
    asm volatile("cp.async.cg.shared.global [%0], [%1], 16;"
                 :: "r"((uint32_t)__cvta_generic_to_shared(dst)), "l"(src));
}
__device__ __forceinline__ void cp_commit() {
    asm volatile("cp.async.commit_group;");
}
__device__ __forceinline__ uint32_t bfpack(float a, float b) {
    __nv_bfloat162 t(__float2bfloat16(a), __float2bfloat16(b));
    return *(uint32_t*)&t;
}
__device__ __forceinline__ uint32_t hfpack(float a, float b) {
    __half2 t(__float2half_rn(a), __float2half_rn(b));
    return *(uint32_t*)&t;
}

// batched fp32 -> bf16 hi/lo split: grid.z selects tensor
struct ConvPtrs { const float4* src[7]; uint2* hi[7]; uint2* lo[7]; int n4[7]; };

__global__ void __launch_bounds__(256)
convert_split_b(ConvPtrs C)
{
    int z = blockIdx.z;
    int i = blockIdx.x * 256 + threadIdx.x;
    if (i >= C.n4[z]) return;
    float4 v = C.src[z][i];
    __nv_bfloat16 hx = __float2bfloat16(v.x), hy = __float2bfloat16(v.y);
    __nv_bfloat16 hz = __float2bfloat16(v.z), hw = __float2bfloat16(v.w);
    __nv_bfloat162 h01(hx, hy), h23(hz, hw);
    C.hi[z][i] = make_uint2(*(uint32_t*)&h01, *(uint32_t*)&h23);
    C.lo[z][i] = make_uint2(bfpack(v.x - __bfloat162float(hx), v.y - __bfloat162float(hy)),
                            bfpack(v.z - __bfloat162float(hz), v.w - __bfloat162float(hw)));
}

// ---------------------------------------------------------------------------
// HMMA GEMM (unchanged)
// ---------------------------------------------------------------------------
struct GemmPtrs {
    const __nv_bfloat16 *Ahi[3], *Alo[3], *Whi[3], *Wlo[3];
    const float* bias[3];
    float* outF[3];
    void *outHi[3], *outLo[3];
    int f16[3];
};

#define GTILE (128*LDK)
#define GSTAGE (4*GTILE)

template<int MODE>
__global__ void __launch_bounds__(256)
gemm_bf16(GemmPtrs P, int M, int N, int K)
{
    extern __shared__ __align__(16) __nv_bfloat16 sm[];
    const int z = (MODE == 0) ? blockIdx.z : 0;
    const __nv_bfloat16* Ahi = P.Ahi[z];
    const __nv_bfloat16* Alo = P.Alo[z];
    const __nv_bfloat16* Whi = P.Whi[z];
    const __nv_bfloat16* Wlo = P.Wlo[z];
    const float* bias = P.bias[z];

    const int tid = threadIdx.x;
    const int wid = tid >> 5;
    const int lane = tid & 31;
    const int wr = wid & 3;
    const int wc = wid >> 2;
    const int m0 = blockIdx.y * 128;
    const int n0 = blockIdx.x * 128;

    wmma::fragment<wmma::accumulator, 16, 16, 16, float> acc[2][4];
#pragma unroll
    for (int i = 0; i < 2; i++)
#pragma unroll
        for (int j = 0; j < 4; j++) wmma::fill_fragment(acc[i][j], 0.f);

    const int NC = K / KC;

    auto stage_copy = [&](int c, int s) {
        const int k0 = c * KC;
        __nv_bfloat16* base = sm + s * GSTAGE;
#pragma unroll
        for (int t = 0; t < 4; t++) {
            int chunk = tid + t * 256;
            int row  = chunk >> 3;
            int coff = (chunk & 7) * 8;
            cp16(base + 0*GTILE + row * LDK + coff, Ahi + (size_t)(m0 + row) * K + k0 + coff);
            cp16(base + 1*GTILE + row * LDK + coff, Alo + (size_t)(m0 + row) * K + k0 + coff);
            cp16(base + 2*GTILE + row * LDK + coff, Whi + (size_t)(n0 + row) * K + k0 + coff);
            cp16(base + 3*GTILE + row * LDK + coff, Wlo + (size_t)(n0 + row) * K + k0 + coff);
        }
        cp_commit();
    };

    stage_copy(0, 0);

    for (int c = 0; c < NC; c++) {
        if (c + 1 < NC) stage_copy(c + 1, (c + 1) & 1);
        if (c + 1 < NC) asm volatile("cp.async.wait_group 1;");
        else            asm volatile("cp.async.wait_group 0;");
        __syncthreads();

        const __nv_bfloat16* base = sm + (c & 1) * GSTAGE;
        const __nv_bfloat16* sAhi = base + 0*GTILE;
        const __nv_bfloat16* sAlo = base + 1*GTILE;
        const __nv_bfloat16* sWhi = base + 2*GTILE;
        const __nv_bfloat16* sWlo = base + 3*GTILE;

#pragma unroll
        for (int kk = 0; kk < KC; kk += 16) {
            wmma::fragment<wmma::matrix_a, 16, 16, 16, __nv_bfloat16, wmma::row_major> aHi[2], aLo[2];
            wmma::fragment<wmma::matrix_b, 16, 16, 16, __nv_bfloat16, wmma::col_major> bHi[4], bLo[4];
#pragma unroll
            for (int i = 0; i < 2; i++) {
                wmma::load_matrix_sync(aHi[i], &sAhi[(wr * 32 + i * 16) * LDK + kk], LDK);
                wmma::load_matrix_sync(aLo[i], &sAlo[(wr * 32 + i * 16) * LDK + kk], LDK);
            }
#pragma unroll
            for (int j = 0; j < 4; j++) {
                wmma::load_matrix_sync(bHi[j], &sWhi[(wc * 64 + j * 16) * LDK + kk], LDK);
                wmma::load_matrix_sync(bLo[j], &sWlo[(wc * 64 + j * 16) * LDK + kk], LDK);
            }
#pragma unroll
            for (int i = 0; i < 2; i++)
#pragma unroll
                for (int j = 0; j < 4; j++) {
                    wmma::mma_sync(acc[i][j], aHi[i], bHi[j], acc[i][j]);
                    wmma::mma_sync(acc[i][j], aHi[i], bLo[j], acc[i][j]);
                    wmma::mma_sync(acc[i][j], aLo[i], bHi[j], acc[i][j]);
                }
        }
        __syncthreads();
    }

    float* scratch = (float*)sm;
    float* ws = scratch + wid * 16 * 20;
    const int er = lane >> 1;
    const int ec = (lane & 1) * 8;

#pragma unroll
    for (int i = 0; i < 2; i++)
#pragma unroll
        for (int j = 0; j < 4; j++) {
            wmma::store_matrix_sync(ws, acc[i][j], 20, wmma::mem_row_major);
            __syncwarp();
            int grow = m0 + wr * 32 + i * 16 + er;
            int col  = n0 + wc * 64 + j * 16 + ec;
            float4 b0 = *(const float4*)&bias[col];
            float4 b1 = *(const float4*)&bias[col + 4];
            float vv[8];
#pragma unroll
            for (int e = 0; e < 4; e++) vv[e]     = ws[er * 20 + ec + e]     + (&b0.x)[e];
#pragma unroll
            for (int e = 0; e < 4; e++) vv[e + 4] = ws[er * 20 + ec + 4 + e] + (&b1.x)[e];

            if (MODE == 0) {
                int b  = grow >> 11;
                int s  = grow & (SEQ - 1);
                int hh = col >> 6;
                int dd = col & (HD - 1);
                size_t off = (((size_t)(b * NH + hh)) * SEQ + s) * HD + dd;
                if (P.f16[z]) {
                    __half h[8];
#pragma unroll
                    for (int e = 0; e < 8; e++) h[e] = __float2half_rn(vv[e]);
                    __half2 p0(h[0],h[1]), p1(h[2],h[3]), p2(h[4],h[5]), p3(h[6],h[7]);
                    uint4 uh = make_uint4(*(uint32_t*)&p0, *(uint32_t*)&p1,
                                          *(uint32_t*)&p2, *(uint32_t*)&p3);
                    uint4 ul;
                    ul.x = hfpack(vv[0]-__half2float(h[0]), vv[1]-__half2float(h[1]));
                    ul.y = hfpack(vv[2]-__half2float(h[2]), vv[3]-__half2float(h[3]));
                    ul.z = hfpack(vv[4]-__half2float(h[4]), vv[5]-__half2float(h[5]));
                    ul.w = hfpack(vv[6]-__half2float(h[6]), vv[7]-__half2float(h[7]));
                    *(uint4*)&((__half*)P.outHi[z])[off] = uh;
                    *(uint4*)&((__half*)P.outLo[z])[off] = ul;
                } else {
                    uint4 uh, ul;
                    __nv_bfloat16 h[8];
#pragma unroll
                    for (int e = 0; e < 8; e++) h[e] = __float2bfloat16(vv[e]);
                    __nv_bfloat162 p0(h[0],h[1]), p1(h[2],h[3]), p2(h[4],h[5]), p3(h[6],h[7]);
                    uh = make_uint4(*(uint32_t*)&p0, *(uint32_t*)&p1, *(uint32_t*)&p2, *(uint32_t*)&p3);
                    ul.x = bfpack(vv[0]-__bfloat162float(h[0]), vv[1]-__bfloat162float(h[1]));
                    ul.y = bfpack(vv[2]-__bfloat162float(h[2]), vv[3]-__bfloat162float(h[3]));
                    ul.z = bfpack(vv[4]-__bfloat162float(h[4]), vv[5]-__bfloat162float(h[5]));
                    ul.w = bfpack(vv[6]-__bfloat162float(h[6]), vv[7]-__bfloat162float(h[7]));
                    *(uint4*)&((__nv_bfloat16*)P.outHi[z])[off] = uh;
                    *(uint4*)&((__nv_bfloat16*)P.outLo[z])[off] = ul;
                }
            } else {
                float* dst = &P.outF[0][(size_t)grow * N + col];
                *(float4*)dst       = make_float4(vv[0], vv[1], vv[2], vv[3]);
                *(float4*)(dst + 4) = make_float4(vv[4], vv[5], vv[6], vv[7]);
            }
            __syncwarp();
        }
}

// ---------------------------------------------------------------------------
// FUSED attention strip: scores phase (R12 structure) then pv phase (R12
// structure) in one CTA. Z passes through smem; pv e-reads hit L2.
// ---------------------------------------------------------------------------
#define SQT (128*LDK)
#define SC_SMEM (6*SQT*2 + 128*STG_LD*4)   // 180224 B (scores layout; pv aliases)
#define PT16 (128*LDK)
#define VT16 (64*LDK)

__global__ void __launch_bounds__(256)
attn_strip(const __nv_bfloat16* __restrict__ qhi, const __nv_bfloat16* __restrict__ qlo,
           const __nv_bfloat16* __restrict__ khi, const __nv_bfloat16* __restrict__ klo,
           const __half* __restrict__ vhi, const __half* __restrict__ vlo,
           const float* __restrict__ res, const float* __restrict__ ph,
           __half* __restrict__ ebuf, float* __restrict__ attn,
           __nv_bfloat16* __restrict__ ctxhi, __nv_bfloat16* __restrict__ ctxlo)
{
    extern __shared__ __align__(16) __nv_bfloat16 smf[];
    __nv_bfloat16* sQhi = smf;
    __nv_bfloat16* sQlo = smf + SQT;
    float* stage = (float*)(smf + 6*SQT);
    __shared__ float invZ[128];

    const int bh = blockIdx.y;
    const int b  = bh >> 4;
    const int h  = bh & (NH - 1);
    const int i0 = blockIdx.x * 128;
    const int tid = threadIdx.x;
    const int wid = tid >> 5;
    const int lane = tid & 31;
    const int wr = wid & 3;
    const int wc = wid >> 2;

    const size_t hbase = (size_t)bh * SEQ * HD;
    const float R  = res[h];
    const float Pp = ph[h];

    // ======================= PHASE 1: scores =======================
#pragma unroll
    for (int t = 0; t < 4; t++) {
        int chunk = tid + t * 256;
        int row  = chunk >> 3;
        int co   = (chunk & 7) * 8;
        cp16(sQhi + row * LDK + co, qhi + hbase + (size_t)(i0 + row) * HD + co);
        cp16(sQlo + row * LDK + co, qlo + hbase + (size_t)(i0 + row) * HD + co);
    }
    cp_commit();

    auto cpK = [&](int jt, int buf) {
        __nv_bfloat16* dKhi = smf + 2*SQT + buf * 2*SQT;
        __nv_bfloat16* dKlo = dKhi + SQT;
        const int j0 = jt * 128;
#pragma unroll
        for (int t = 0; t < 4; t++) {
            int chunk = tid + t * 256;
            int row  = chunk >> 3;
            int co   = (chunk & 7) * 8;
            cp16(dKhi + row * LDK + co, khi + hbase + (size_t)(j0 + row) * HD + co);
            cp16(dKlo + row * LDK + co, klo + hbase + (size_t)(j0 + row) * HD + co);
        }
        cp_commit();
    };

    cpK(0, 0);

    const int row_e = tid >> 1;
    const int c0_e  = (tid & 1) * 64;
    float zsum = 0.f;

    for (int jt = 0; jt < JT; jt++) {
        asm volatile("cp.async.wait_group 0;");
        __syncthreads();
        if (jt + 1 < JT) cpK(jt + 1, (jt + 1) & 1);

        const __nv_bfloat16* sKhi = smf + 2*SQT + (jt & 1) * 2*SQT;
        const __nv_bfloat16* sKlo = sKhi + SQT;

        wmma::fragment<wmma::accumulator, 16, 16, 16, float> acc[2][4];
#pragma unroll
        for (int i = 0; i < 2; i++)
#pragma unroll
            for (int j = 0; j < 4; j++) wmma::fill_fragment(acc[i][j], 0.f);

#pragma unroll
        for (int kk = 0; kk < 64; kk += 16) {
            wmma::fragment<wmma::matrix_a, 16, 16, 16, __nv_bfloat16, wmma::row_major> aHi[2], aLo[2];
            wmma::fragment<wmma::matrix_b, 16, 16, 16, __nv_bfloat16, wmma::col_major> bHi[4], bLo[4];
#pragma unroll
            for (int i = 0; i < 2; i++) {
                wmma::load_matrix_sync(aHi[i], &sQhi[(wr * 32 + i * 16) * LDK + kk], LDK);
                wmma::load_matrix_sync(aLo[i], &sQlo[(wr * 32 + i * 16) * LDK + kk], LDK);
            }
#pragma unroll
            for (int j = 0; j < 4; j++) {
                wmma::load_matrix_sync(bHi[j], &sKhi[(wc * 64 + j * 16) * LDK + kk], LDK);
                wmma::load_matrix_sync(bLo[j], &sKlo[(wc * 64 + j * 16) * LDK + kk], LDK);
            }
#pragma unroll
            for (int i = 0; i < 2; i++)
#pragma unroll
                for (int j = 0; j < 4; j++) {
                    wmma::mma_sync(acc[i][j], aHi[i], bHi[j], acc[i][j]);
                    wmma::mma_sync(acc[i][j], aHi[i], bLo[j], acc[i][j]);
                    wmma::mma_sync(acc[i][j], aLo[i], bHi[j], acc[i][j]);
                }
        }

#pragma unroll
        for (int i = 0; i < 2; i++)
#pragma unroll
            for (int j = 0; j < 4; j++)
#pragma unroll
                for (int e = 0; e < acc[i][j].num_elements; e++) {
                    float s = acc[i][j].x[e] * 0.125f;
                    s += R * __sinf(s + Pp);
                    acc[i][j].x[e] = __expf(s);
                }

#pragma unroll
        for (int i = 0; i < 2; i++)
#pragma unroll
            for (int j = 0; j < 4; j++)
                wmma::store_matrix_sync(&stage[(size_t)(wr * 32 + i * 16) * STG_LD + wc * 64 + j * 16],
                                        acc[i][j], STG_LD, wmma::mem_row_major);
        __syncthreads();

        {
            const float* pr = &stage[(size_t)row_e * STG_LD + c0_e];
            __half* erow = ebuf + ((size_t)bh * SEQ + i0 + row_e) * SEQ + jt * 128 + c0_e;
#pragma unroll
            for (int c = 0; c < 64; c += 8) {
                float4 v0 = *(const float4*)&pr[c];
                float4 v1 = *(const float4*)&pr[c + 4];
                zsum += v0.x + v0.y + v0.z + v0.w + v1.x + v1.y + v1.z + v1.w;
                __half2 e0 = __floats2half2_rn(v0.x, v0.y);
                __half2 e1 = __floats2half2_rn(v0.z, v0.w);
                __half2 e2 = __floats2half2_rn(v1.x, v1.y);
                __half2 e3 = __floats2half2_rn(v1.z, v1.w);
                *(uint4*)&erow[c] = make_uint4(*(uint32_t*)&e0, *(uint32_t*)&e1,
                                               *(uint32_t*)&e2, *(uint32_t*)&e3);
            }
        }
    }

    zsum += __shfl_xor_sync(0xffffffffu, zsum, 1);
    if ((tid & 1) == 0) invZ[row_e] = 1.f / zsum;
    __syncthreads();

    // ======================= PHASE 2: pv =======================
    __half* smp  = (__half*)smf;
    __half* sP   = smp;
    __half* sVhi = smp + PT16;
    __half* sVlo = smp + PT16 + VT16;

    const __half* Eb = ebuf + ((size_t)bh * SEQ + i0) * SEQ;
    float* Ab = attn + ((size_t)bh * SEQ + i0) * SEQ;
    const __half* Vbh = vhi + hbase;
    const __half* Vbl = vlo + hbase;

    wmma::fragment<wmma::accumulator, 16, 16, 16, float> accO[2][2];
#pragma unroll
    for (int i = 0; i < 2; i++)
#pragma unroll
        for (int j = 0; j < 2; j++) wmma::fill_fragment(accO[i][j], 0.f);

    for (int k0 = 0; k0 < SEQ; k0 += 64) {
#pragma unroll
        for (int t = 0; t < 2; t++) {
            int slot = tid + t * 256;
            int row  = slot >> 3;
            int co   = (slot & 7) * 8;
            cp16(sVhi + row * LDK + co, Vbh + (size_t)(k0 + row) * HD + co);
            cp16(sVlo + row * LDK + co, Vbl + (size_t)(k0 + row) * HD + co);
        }
        cp_commit();

#pragma unroll
        for (int t = 0; t < 4; t++) {
            int slot = tid + t * 256;
            int row  = slot >> 3;
            int c8   = (slot & 7) * 8;
            float iz = invZ[row];
            uint4 raw = *(const uint4*)&Eb[(size_t)row * SEQ + k0 + c8];
            *(uint4*)&sP[row * LDK + c8] = raw;
            float2 f0 = __half22float2(*(__half2*)&raw.x);
            float2 f1 = __half22float2(*(__half2*)&raw.y);
            float2 f2 = __half22float2(*(__half2*)&raw.z);
            float2 f3 = __half22float2(*(__half2*)&raw.w);
            *(float4*)&Ab[(size_t)row * SEQ + k0 + c8] =
                make_float4(f0.x*iz, f0.y*iz, f1.x*iz, f1.y*iz);
            *(float4*)&Ab[(size_t)row * SEQ + k0 + c8 + 4] =
                make_float4(f2.x*iz, f2.y*iz, f3.x*iz, f3.y*iz);
        }
        asm volatile("cp.async.wait_group 0;");
        __syncthreads();

#pragma unroll
        for (int kk = 0; kk < 64; kk += 16) {
            wmma::fragment<wmma::matrix_a, 16, 16, 16, __half, wmma::row_major> aP[2];
            wmma::fragment<wmma::matrix_b, 16, 16, 16, __half, wmma::row_major> bHi[2], bLo[2];
#pragma unroll
            for (int i = 0; i < 2; i++)
                wmma::load_matrix_sync(aP[i], &sP[(wr * 32 + i * 16) * LDK + kk], LDK);
#pragma unroll
            for (int j = 0; j < 2; j++) {
                wmma::load_matrix_sync(bHi[j], &sVhi[kk * LDK + wc * 32 + j * 16], LDK);
                wmma::load_matrix_sync(bLo[j], &sVlo[kk * LDK + wc * 32 + j * 16], LDK);
            }
#pragma unroll
            for (int i = 0; i < 2; i++)
#pragma unroll
                for (int j = 0; j < 2; j++) {
                    wmma::mma_sync(accO[i][j], aP[i], bHi[j], accO[i][j]);
                    wmma::mma_sync(accO[i][j], aP[i], bLo[j], accO[i][j]);
                }
        }
        __syncthreads();
    }

    // Epilogue: scale by invZ, ctx hi/lo
    float* ws = ((float*)smp) + wid * 16 * 20;
    const int er = lane >> 1;
    const int ec = (lane & 1) * 8;

#pragma unroll
    for (int i = 0; i < 2; i++)
#pragma unroll
        for (int j = 0; j < 2; j++) {
            wmma::store_matrix_sync(ws, accO[i][j], 20, wmma::mem_row_major);
            __syncwarp();
            int rl  = wr * 32 + i * 16 + er;
            int col = wc * 32 + j * 16 + ec;
            float iz = invZ[rl];
            size_t off = ((size_t)b * SEQ + i0 + rl) * DM + h * HD + col;
            float vv[8];
#pragma unroll
            for (int e = 0; e < 8; e++) vv[e] = ws[er * 20 + ec + e] * iz;
            __nv_bfloat16 hh[8];
#pragma unroll
            for (int e = 0; e < 8; e++) hh[e] = __float2bfloat16(vv[e]);
            __nv_bfloat162 p0(hh[0],hh[1]), p1(hh[2],hh[3]), p2(hh[4],hh[5]), p3(hh[6],hh[7]);
            *(uint4*)&ctxhi[off] = make_uint4(*(uint32_t*)&p0, *(uint32_t*)&p1,
                                              *(uint32_t*)&p2, *(uint32_t*)&p3);
            uint4 ul;
            ul.x = bfpack(vv[0]-__bfloat162float(hh[0]), vv[1]-__bfloat162float(hh[1]));
            ul.y = bfpack(vv[2]-__bfloat162float(hh[2]), vv[3]-__bfloat162float(hh[3]));
            ul.z = bfpack(vv[4]-__bfloat162float(hh[4]), vv[5]-__bfloat162float(hh[5]));
            ul.w = bfpack(vv[6]-__bfloat162float(hh[6]), vv[7]-__bfloat162float(hh[7]));
            *(uint4*)&ctxlo[off] = ul;
            __syncwarp();
        }
}

// ---------------------------------------------------------------------------
// Launch
// ---------------------------------------------------------------------------
extern "C" void kernel_launch(void* const* d_in, const int* in_sizes, int n_in,
                              void* d_out, int out_size)
{
    const float* query = (const float*)d_in[0];
    const float* key   = (const float*)d_in[1];
    const float* value = (const float*)d_in[2];
    const float* Wq    = (const float*)d_in[3];
    const float* bq    = (const float*)d_in[4];
    const float* Wk    = (const float*)d_in[5];
    const float* bk    = (const float*)d_in[6];
    const float* Wv    = (const float*)d_in[7];
    const float* bv    = (const float*)d_in[8];
    const float* Wo    = (const float*)d_in[9];
    const float* bo    = (const float*)d_in[10];
    const float* reso  = (const float*)d_in[11];
    const float* phas  = (const float*)d_in[12];

    __nv_bfloat16 *xqh,*xql,*xkh,*xkl,*xvh,*xvl, *wqh,*wql,*wkh,*wkl,*wvh,*wvl,*woh,*wol;
    __nv_bfloat16 *qh,*ql,*kh,*kl, *cxh,*cxl;
    __half *vh,*vl, *eb;
    float *scratch;
    cudaGetSymbolAddress((void**)&xqh, g_xq_hi); cudaGetSymbolAddress((void**)&xql, g_xq_lo);
    cudaGetSymbolAddress((void**)&xkh, g_xk_hi); cudaGetSymbolAddress((void**)&xkl, g_xk_lo);
    cudaGetSymbolAddress((void**)&xvh, g_xv_hi); cudaGetSymbolAddress((void**)&xvl, g_xv_lo);
    cudaGetSymbolAddress((void**)&wqh, g_wq_hi); cudaGetSymbolAddress((void**)&wql, g_wq_lo);
    cudaGetSymbolAddress((void**)&wkh, g_wk_hi); cudaGetSymbolAddress((void**)&wkl, g_wk_lo);
    cudaGetSymbolAddress((void**)&wvh, g_wv_hi); cudaGetSymbolAddress((void**)&wvl, g_wv_lo);
    cudaGetSymbolAddress((void**)&woh, g_wo_hi); cudaGetSymbolAddress((void**)&wol, g_wo_lo);
    cudaGetSymbolAddress((void**)&qh,  g_q_hi);  cudaGetSymbolAddress((void**)&ql,  g_q_lo);
    cudaGetSymbolAddress((void**)&kh,  g_k_hi);  cudaGetSymbolAddress((void**)&kl,  g_k_lo);
    cudaGetSymbolAddress((void**)&vh,  g_v_hi);  cudaGetSymbolAddress((void**)&vl,  g_v_lo);
    cudaGetSymbolAddress((void**)&cxh, g_ctx_hi); cudaGetSymbolAddress((void**)&cxl, g_ctx_lo);
    cudaGetSymbolAddress((void**)&eb,  g_e);
    cudaGetSymbolAddress((void**)&scratch, g_attn_scratch);

    float* out_ptr = (float*)d_out;
    const bool attn_in_out = ((size_t)out_size >= OUT_ELEMS + ATTN_ELEMS);
    float* attn_ptr = attn_in_out ? (out_ptr + OUT_ELEMS) : scratch;

    const int GEMM_SMEM = 2 * GSTAGE * 2;
    cudaFuncSetAttribute(gemm_bf16<0>, cudaFuncAttributeMaxDynamicSharedMemorySize, GEMM_SMEM);
    cudaFuncSetAttribute(gemm_bf16<1>, cudaFuncAttributeMaxDynamicSharedMemorySize, GEMM_SMEM);
    cudaFuncSetAttribute(attn_strip,   cudaFuncAttributeMaxDynamicSharedMemorySize, SC_SMEM);

    // 0) batched split fp32 -> bf16 hi/lo (one launch)
    const int NX4 = MTOT * DM / 4, NW4 = DM * DM / 4;
    ConvPtrs C = {};
    C.src[0]=(const float4*)query; C.hi[0]=(uint2*)xqh; C.lo[0]=(uint2*)xql; C.n4[0]=NX4;
    C.src[1]=(const float4*)key;   C.hi[1]=(uint2*)xkh; C.lo[1]=(uint2*)xkl; C.n4[1]=NX4;
    C.src[2]=(const float4*)value; C.hi[2]=(uint2*)xvh; C.lo[2]=(uint2*)xvl; C.n4[2]=NX4;
    C.src[3]=(const float4*)Wq;    C.hi[3]=(uint2*)wqh; C.lo[3]=(uint2*)wql; C.n4[3]=NW4;
    C.src[4]=(const float4*)Wk;    C.hi[4]=(uint2*)wkh; C.lo[4]=(uint2*)wkl; C.n4[4]=NW4;
    C.src[5]=(const float4*)Wv;    C.hi[5]=(uint2*)wvh; C.lo[5]=(uint2*)wvl; C.n4[5]=NW4;
    C.src[6]=(const float4*)Wo;    C.hi[6]=(uint2*)woh; C.lo[6]=(uint2*)wol; C.n4[6]=NW4;
    dim3 gC((NX4 + 255) / 256, 1, 7);
    convert_split_b<<<gC, 256>>>(C);

    // 1) QKV projections (q,k bf16 hi/lo; v fp16 hi/lo)
    GemmPtrs Pq = {};
    Pq.Ahi[0]=xqh; Pq.Alo[0]=xql; Pq.Whi[0]=wqh; Pq.Wlo[0]=wql; Pq.bias[0]=bq;
    Pq.outHi[0]=qh; Pq.outLo[0]=ql; Pq.f16[0]=0;
    Pq.Ahi[1]=xkh; Pq.Alo[1]=xkl; Pq.Whi[1]=wkh; Pq.Wlo[1]=wkl; Pq.bias[1]=bk;
    Pq.outHi[1]=kh; Pq.outLo[1]=kl; Pq.f16[1]=0;
    Pq.Ahi[2]=xvh; Pq.Alo[2]=xvl; Pq.Whi[2]=wvh; Pq.Wlo[2]=wvl; Pq.bias[2]=bv;
    Pq.outHi[2]=vh; Pq.outLo[2]=vl; Pq.f16[2]=1;
    dim3 gP(DM / 128, MTOT / 128, 3);
    gemm_bf16<0><<<gP, 256, GEMM_SMEM>>>(Pq, MTOT, DM, DM);

    // 2) FUSED scores + softmax + PV + attn write
    dim3 gF(SEQ / 128, BATCH * NH);
    attn_strip<<<gF, 256, SC_SMEM>>>(qh, ql, kh, kl, vh, vl, reso, phas,
                                     eb, attn_ptr, cxh, cxl);

    // 3) Output projection -> d_out
    GemmPtrs Po = {};
    Po.Ahi[0]=cxh; Po.Alo[0]=cxl; Po.Whi[0]=woh; Po.Wlo[0]=wol; Po.bias[0]=bo;
    Po.outF[0]=out_ptr;
    dim3 gO(DM / 128, MTOT / 128, 1);
    gemm_bf16<1><<<gO, 256, GEMM_SMEM>>>(Po, MTOT, DM, DM);
}

// round 15
// speedup vs baseline: 1.1334x; 1.1334x over previous
#include <cuda_runtime.h>
#include <cuda_bf16.h>
#include <cuda_fp16.h>
#include <mma.h>
#include <math.h>
#include <stdint.h>

using namespace nvcuda;

#define BATCH 2
#define SEQ   2048
#define DM    1024
#define NH    16
#define HD    64
#define MTOT  (BATCH*SEQ)
#define JT    (SEQ/128)
#define LDK   72
#define STG_LD 136

static const size_t OUT_ELEMS  = (size_t)BATCH * SEQ * DM;
static const size_t ATTN_ELEMS = (size_t)BATCH * NH * SEQ * SEQ;

// ---------------------------------------------------------------------------
// Device scratch
// ---------------------------------------------------------------------------
__device__ __nv_bfloat16 g_xq_hi[MTOT*DM], g_xq_lo[MTOT*DM];
__device__ __nv_bfloat16 g_xk_hi[MTOT*DM], g_xk_lo[MTOT*DM];
__device__ __nv_bfloat16 g_xv_hi[MTOT*DM], g_xv_lo[MTOT*DM];
__device__ __nv_bfloat16 g_wq_hi[DM*DM], g_wq_lo[DM*DM];
__device__ __nv_bfloat16 g_wk_hi[DM*DM], g_wk_lo[DM*DM];
__device__ __nv_bfloat16 g_wv_hi[DM*DM], g_wv_lo[DM*DM];
__device__ __nv_bfloat16 g_wo_hi[DM*DM], g_wo_lo[DM*DM];
__device__ __nv_bfloat16 g_q_hi[BATCH*NH*SEQ*HD], g_q_lo[BATCH*NH*SEQ*HD];
__device__ __nv_bfloat16 g_k_hi[BATCH*NH*SEQ*HD], g_k_lo[BATCH*NH*SEQ*HD];
__device__ __half        g_v_hi[BATCH*NH*SEQ*HD], g_v_lo[BATCH*NH*SEQ*HD];
__device__ __nv_bfloat16 g_ctx_hi[MTOT*DM], g_ctx_lo[MTOT*DM];
__device__ __half g_e[(size_t)BATCH*NH*SEQ*SEQ];
__device__ float g_z[(size_t)BATCH*NH*SEQ];
__device__ float g_attn_scratch[(size_t)BATCH*NH*SEQ*SEQ];

// ---------------------------------------------------------------------------
// Helpers
// ---------------------------------------------------------------------------
__device__ __forceinline__ void cp16(void* dst, const void* src) {
    asm volatile("cp.async.cg.shared.global [%0], [%1], 16;"
                 :: "r"((uint32_t)__cvta_generic_to_shared(dst)), "l"(src));
}
__device__ __forceinline__ void cp_commit() {
    asm volatile("cp.async.commit_group;");
}
__device__ __forceinline__ uint32_t bfpack(float a, float b) {
    __nv_bfloat162 t(__float2bfloat16(a), __float2bfloat16(b));
    return *(uint32_t*)&t;
}
__device__ __forceinline__ uint32_t hfpack(float a, float b) {
    __half2 t(__float2half_rn(a), __float2half_rn(b));
    return *(uint32_t*)&t;
}

// batched fp32 -> bf16 hi/lo split: grid.z selects tensor
struct ConvPtrs { const float4* src[7]; uint2* hi[7]; uint2* lo[7]; int n4[7]; };

__global__ void __launch_bounds__(256)
convert_split_b(ConvPtrs C)
{
    int z = blockIdx.z;
    int i = blockIdx.x * 256 + threadIdx.x;
    if (i >= C.n4[z]) return;
    float4 v = C.src[z][i];
    __nv_bfloat16 hx = __float2bfloat16(v.x), hy = __float2bfloat16(v.y);
    __nv_bfloat16 hz = __float2bfloat16(v.z), hw = __float2bfloat16(v.w);
    __nv_bfloat162 h01(hx, hy), h23(hz, hw);
    C.hi[z][i] = make_uint2(*(uint32_t*)&h01, *(uint32_t*)&h23);
    C.lo[z][i] = make_uint2(bfpack(v.x - __bfloat162float(hx), v.y - __bfloat162float(hy)),
                            bfpack(v.z - __bfloat162float(hz), v.w - __bfloat162float(hw)));
}

// ---------------------------------------------------------------------------
// HMMA GEMM, KC=32 chunks, 2 CTAs/SM (82KB smem, regs capped at 128).
// ---------------------------------------------------------------------------
struct GemmPtrs {
    const __nv_bfloat16 *Ahi[3], *Alo[3], *Whi[3], *Wlo[3];
    const float* bias[3];
    float* outF[3];
    void *outHi[3], *outLo[3];
    int f16[3];
};

#define KCG 32
#define LDG2 40                 // 32 + 8 pad
#define GTILE (128*LDG2)        // 5120 elems
#define GSTAGE (4*GTILE)        // 20480 elems = 40960 B

template<int MODE>
__global__ void __launch_bounds__(256, 2)
gemm_bf16(GemmPtrs P, int M, int N, int K)
{
    extern __shared__ __align__(16) __nv_bfloat16 sm[];
    const int z = (MODE == 0) ? blockIdx.z : 0;
    const __nv_bfloat16* Ahi = P.Ahi[z];
    const __nv_bfloat16* Alo = P.Alo[z];
    const __nv_bfloat16* Whi = P.Whi[z];
    const __nv_bfloat16* Wlo = P.Wlo[z];
    const float* bias = P.bias[z];

    const int tid = threadIdx.x;
    const int wid = tid >> 5;
    const int lane = tid & 31;
    const int wr = wid & 3;
    const int wc = wid >> 2;
    const int m0 = blockIdx.y * 128;
    const int n0 = blockIdx.x * 128;

    wmma::fragment<wmma::accumulator, 16, 16, 16, float> acc[2][4];
#pragma unroll
    for (int i = 0; i < 2; i++)
#pragma unroll
        for (int j = 0; j < 4; j++) wmma::fill_fragment(acc[i][j], 0.f);

    const int NC = K / KCG;   // 32

    auto stage_copy = [&](int c, int s) {
        const int k0 = c * KCG;
        __nv_bfloat16* base = sm + s * GSTAGE;
#pragma unroll
        for (int t = 0; t < 2; t++) {
            int slot = tid + t * 256;          // 0..511
            int row  = slot >> 2;              // 0..127
            int coff = (slot & 3) * 8;         // 0..24
            cp16(base + 0*GTILE + row * LDG2 + coff, Ahi + (size_t)(m0 + row) * K + k0 + coff);
            cp16(base + 1*GTILE + row * LDG2 + coff, Alo + (size_t)(m0 + row) * K + k0 + coff);
            cp16(base + 2*GTILE + row * LDG2 + coff, Whi + (size_t)(n0 + row) * K + k0 + coff);
            cp16(base + 3*GTILE + row * LDG2 + coff, Wlo + (size_t)(n0 + row) * K + k0 + coff);
        }
        cp_commit();
    };

    stage_copy(0, 0);

    for (int c = 0; c < NC; c++) {
        if (c + 1 < NC) stage_copy(c + 1, (c + 1) & 1);
        if (c + 1 < NC) asm volatile("cp.async.wait_group 1;");
        else            asm volatile("cp.async.wait_group 0;");
        __syncthreads();

        const __nv_bfloat16* base = sm + (c & 1) * GSTAGE;
        const __nv_bfloat16* sAhi = base + 0*GTILE;
        const __nv_bfloat16* sAlo = base + 1*GTILE;
        const __nv_bfloat16* sWhi = base + 2*GTILE;
        const __nv_bfloat16* sWlo = base + 3*GTILE;

#pragma unroll
        for (int kk = 0; kk < KCG; kk += 16) {
            wmma::fragment<wmma::matrix_a, 16, 16, 16, __nv_bfloat16, wmma::row_major> aHi[2], aLo[2];
            wmma::fragment<wmma::matrix_b, 16, 16, 16, __nv_bfloat16, wmma::col_major> bHi[4], bLo[4];
#pragma unroll
            for (int i = 0; i < 2; i++) {
                wmma::load_matrix_sync(aHi[i], &sAhi[(wr * 32 + i * 16) * LDG2 + kk], LDG2);
                wmma::load_matrix_sync(aLo[i], &sAlo[(wr * 32 + i * 16) * LDG2 + kk], LDG2);
            }
#pragma unroll
            for (int j = 0; j < 4; j++) {
                wmma::load_matrix_sync(bHi[j], &sWhi[(wc * 64 + j * 16) * LDG2 + kk], LDG2);
                wmma::load_matrix_sync(bLo[j], &sWlo[(wc * 64 + j * 16) * LDG2 + kk], LDG2);
            }
#pragma unroll
            for (int i = 0; i < 2; i++)
#pragma unroll
                for (int j = 0; j < 4; j++) {
                    wmma::mma_sync(acc[i][j], aHi[i], bHi[j], acc[i][j]);
                    wmma::mma_sync(acc[i][j], aHi[i], bLo[j], acc[i][j]);
                    wmma::mma_sync(acc[i][j], aLo[i], bHi[j], acc[i][j]);
                }
        }
        __syncthreads();
    }

    float* scratch = (float*)sm;
    float* ws = scratch + wid * 16 * 20;
    const int er = lane >> 1;
    const int ec = (lane & 1) * 8;

#pragma unroll
    for (int i = 0; i < 2; i++)
#pragma unroll
        for (int j = 0; j < 4; j++) {
            wmma::store_matrix_sync(ws, acc[i][j], 20, wmma::mem_row_major);
            __syncwarp();
            int grow = m0 + wr * 32 + i * 16 + er;
            int col  = n0 + wc * 64 + j * 16 + ec;
            float4 b0 = *(const float4*)&bias[col];
            float4 b1 = *(const float4*)&bias[col + 4];
            float vv[8];
#pragma unroll
            for (int e = 0; e < 4; e++) vv[e]     = ws[er * 20 + ec + e]     + (&b0.x)[e];
#pragma unroll
            for (int e = 0; e < 4; e++) vv[e + 4] = ws[er * 20 + ec + 4 + e] + (&b1.x)[e];

            if (MODE == 0) {
                int b  = grow >> 11;
                int s  = grow & (SEQ - 1);
                int hh = col >> 6;
                int dd = col & (HD - 1);
                size_t off = (((size_t)(b * NH + hh)) * SEQ + s) * HD + dd;
                if (P.f16[z]) {
                    __half h[8];
#pragma unroll
                    for (int e = 0; e < 8; e++) h[e] = __float2half_rn(vv[e]);
                    __half2 p0(h[0],h[1]), p1(h[2],h[3]), p2(h[4],h[5]), p3(h[6],h[7]);
                    uint4 uh = make_uint4(*(uint32_t*)&p0, *(uint32_t*)&p1,
                                          *(uint32_t*)&p2, *(uint32_t*)&p3);
                    uint4 ul;
                    ul.x = hfpack(vv[0]-__half2float(h[0]), vv[1]-__half2float(h[1]));
                    ul.y = hfpack(vv[2]-__half2float(h[2]), vv[3]-__half2float(h[3]));
                    ul.z = hfpack(vv[4]-__half2float(h[4]), vv[5]-__half2float(h[5]));
                    ul.w = hfpack(vv[6]-__half2float(h[6]), vv[7]-__half2float(h[7]));
                    *(uint4*)&((__half*)P.outHi[z])[off] = uh;
                    *(uint4*)&((__half*)P.outLo[z])[off] = ul;
                } else {
                    uint4 uh, ul;
                    __nv_bfloat16 h[8];
#pragma unroll
                    for (int e = 0; e < 8; e++) h[e] = __float2bfloat16(vv[e]);
                    __nv_bfloat162 p0(h[0],h[1]), p1(h[2],h[3]), p2(h[4],h[5]), p3(h[6],h[7]);
                    uh = make_uint4(*(uint32_t*)&p0, *(uint32_t*)&p1, *(uint32_t*)&p2, *(uint32_t*)&p3);
                    ul.x = bfpack(vv[0]-__bfloat162float(h[0]), vv[1]-__bfloat162float(h[1]));
                    ul.y = bfpack(vv[2]-__bfloat162float(h[2]), vv[3]-__bfloat162float(h[3]));
                    ul.z = bfpack(vv[4]-__bfloat162float(h[4]), vv[5]-__bfloat162float(h[5]));
                    ul.w = bfpack(vv[6]-__bfloat162float(h[6]), vv[7]-__bfloat162float(h[7]));
                    *(uint4*)&((__nv_bfloat16*)P.outHi[z])[off] = uh;
                    *(uint4*)&((__nv_bfloat16*)P.outLo[z])[off] = ul;
                }
            } else {
                float* dst = &P.outF[0][(size_t)grow * N + col];
                *(float4*)dst       = make_float4(vv[0], vv[1], vv[2], vv[3]);
                *(float4*)(dst + 4) = make_float4(vv[4], vv[5], vv[6], vv[7]);
            }
            __syncwarp();
        }
}

// ---------------------------------------------------------------------------
// Scores, STRIP-PERSISTENT (R12 exact)
// ---------------------------------------------------------------------------
#define SQT (128*LDK)
#define SC_SMEM (6*SQT*2 + 128*STG_LD*4)

__global__ void __launch_bounds__(256)
scores_strip(const __nv_bfloat16* __restrict__ qhi, const __nv_bfloat16* __restrict__ qlo,
             const __nv_bfloat16* __restrict__ khi, const __nv_bfloat16* __restrict__ klo,
             const float* __restrict__ res, const float* __restrict__ ph,
             __half* __restrict__ ebuf, float* __restrict__ zout)
{
    extern __shared__ __align__(16) __nv_bfloat16 smf[];
    __nv_bfloat16* sQhi = smf;
    __nv_bfloat16* sQlo = smf + SQT;
    float* stage = (float*)(smf + 6*SQT);

    const int bh = blockIdx.y;
    const int h  = bh & (NH - 1);
    const int i0 = blockIdx.x * 128;
    const int tid = threadIdx.x;
    const int wid = tid >> 5;
    const int wr = wid & 3;
    const int wc = wid >> 2;

    const size_t hbase = (size_t)bh * SEQ * HD;
    const float R  = res[h];
    const float Pp = ph[h];

#pragma unroll
    for (int t = 0; t < 4; t++) {
        int chunk = tid + t * 256;
        int row  = chunk >> 3;
        int co   = (chunk & 7) * 8;
        cp16(sQhi + row * LDK + co, qhi + hbase + (size_t)(i0 + row) * HD + co);
        cp16(sQlo + row * LDK + co, qlo + hbase + (size_t)(i0 + row) * HD + co);
    }
    cp_commit();

    auto cpK = [&](int jt, int buf) {
        __nv_bfloat16* dKhi = smf + 2*SQT + buf * 2*SQT;
        __nv_bfloat16* dKlo = dKhi + SQT;
        const int j0 = jt * 128;
#pragma unroll
        for (int t = 0; t < 4; t++) {
            int chunk = tid + t * 256;
            int row  = chunk >> 3;
            int co   = (chunk & 7) * 8;
            cp16(dKhi + row * LDK + co, khi + hbase + (size_t)(j0 + row) * HD + co);
            cp16(dKlo + row * LDK + co, klo + hbase + (size_t)(j0 + row) * HD + co);
        }
        cp_commit();
    };

    cpK(0, 0);

    const int row_e = tid >> 1;
    const int c0_e  = (tid & 1) * 64;
    float zsum = 0.f;

    for (int jt = 0; jt < JT; jt++) {
        asm volatile("cp.async.wait_group 0;");
        __syncthreads();
        if (jt + 1 < JT) cpK(jt + 1, (jt + 1) & 1);

        const __nv_bfloat16* sKhi = smf + 2*SQT + (jt & 1) * 2*SQT;
        const __nv_bfloat16* sKlo = sKhi + SQT;

        wmma::fragment<wmma::accumulator, 16, 16, 16, float> acc[2][4];
#pragma unroll
        for (int i = 0; i < 2; i++)
#pragma unroll
            for (int j = 0; j < 4; j++) wmma::fill_fragment(acc[i][j], 0.f);

#pragma unroll
        for (int kk = 0; kk < 64; kk += 16) {
            wmma::fragment<wmma::matrix_a, 16, 16, 16, __nv_bfloat16, wmma::row_major> aHi[2], aLo[2];
            wmma::fragment<wmma::matrix_b, 16, 16, 16, __nv_bfloat16, wmma::col_major> bHi[4], bLo[4];
#pragma unroll
            for (int i = 0; i < 2; i++) {
                wmma::load_matrix_sync(aHi[i], &sQhi[(wr * 32 + i * 16) * LDK + kk], LDK);
                wmma::load_matrix_sync(aLo[i], &sQlo[(wr * 32 + i * 16) * LDK + kk], LDK);
            }
#pragma unroll
            for (int j = 0; j < 4; j++) {
                wmma::load_matrix_sync(bHi[j], &sKhi[(wc * 64 + j * 16) * LDK + kk], LDK);
                wmma::load_matrix_sync(bLo[j], &sKlo[(wc * 64 + j * 16) * LDK + kk], LDK);
            }
#pragma unroll
            for (int i = 0; i < 2; i++)
#pragma unroll
                for (int j = 0; j < 4; j++) {
                    wmma::mma_sync(acc[i][j], aHi[i], bHi[j], acc[i][j]);
                    wmma::mma_sync(acc[i][j], aHi[i], bLo[j], acc[i][j]);
                    wmma::mma_sync(acc[i][j], aLo[i], bHi[j], acc[i][j]);
                }
        }

#pragma unroll
        for (int i = 0; i < 2; i++)
#pragma unroll
            for (int j = 0; j < 4; j++)
#pragma unroll
                for (int e = 0; e < acc[i][j].num_elements; e++) {
                    float s = acc[i][j].x[e] * 0.125f;
                    s += R * __sinf(s + Pp);
                    acc[i][j].x[e] = __expf(s);
                }

#pragma unroll
        for (int i = 0; i < 2; i++)
#pragma unroll
            for (int j = 0; j < 4; j++)
                wmma::store_matrix_sync(&stage[(size_t)(wr * 32 + i * 16) * STG_LD + wc * 64 + j * 16],
                                        acc[i][j], STG_LD, wmma::mem_row_major);
        __syncthreads();

        {
            const float* pr = &stage[(size_t)row_e * STG_LD + c0_e];
            __half* erow = ebuf + ((size_t)bh * SEQ + i0 + row_e) * SEQ + jt * 128 + c0_e;
#pragma unroll
            for (int c = 0; c < 64; c += 8) {
                float4 v0 = *(const float4*)&pr[c];
                float4 v1 = *(const float4*)&pr[c + 4];
                zsum += v0.x + v0.y + v0.z + v0.w + v1.x + v1.y + v1.z + v1.w;
                __half2 e0 = __floats2half2_rn(v0.x, v0.y);
                __half2 e1 = __floats2half2_rn(v0.z, v0.w);
                __half2 e2 = __floats2half2_rn(v1.x, v1.y);
                __half2 e3 = __floats2half2_rn(v1.z, v1.w);
                *(uint4*)&erow[c] = make_uint4(*(uint32_t*)&e0, *(uint32_t*)&e1,
                                               *(uint32_t*)&e2, *(uint32_t*)&e3);
            }
        }
    }

    zsum += __shfl_xor_sync(0xffffffffu, zsum, 1);
    if ((tid & 1) == 0)
        zout[(size_t)bh * SEQ + i0 + row_e] = zsum;
}

// ---------------------------------------------------------------------------
// PV on fp16 HMMA (R12 exact)
// ---------------------------------------------------------------------------
#define PT16 (128*LDK)
#define VT16 (64*LDK)
#define PV_SMEM ((PT16 + 2*VT16) * 2)

__global__ void __launch_bounds__(256)
pv_wmma(const __half* __restrict__ ebuf, float* __restrict__ attn,
        const __half* __restrict__ vhi, const __half* __restrict__ vlo,
        const float* __restrict__ zfull,
        __nv_bfloat16* __restrict__ ctxhi, __nv_bfloat16* __restrict__ ctxlo)
{
    extern __shared__ __align__(16) __half smp[];
    __half* sP   = smp;
    __half* sVhi = smp + PT16;
    __half* sVlo = smp + PT16 + VT16;
    __shared__ float invZ[128];

    const int bh = blockIdx.y;
    const int b  = bh >> 4;
    const int h  = bh & 15;
    const int i0 = blockIdx.x * 128;
    const int tid = threadIdx.x;
    const int wid = tid >> 5;
    const int lane = tid & 31;
    const int wr = wid & 3;
    const int wc = wid >> 2;

    if (tid < 128)
        invZ[tid] = 1.f / zfull[(size_t)bh * SEQ + i0 + tid];
    __syncthreads();

    const __half* Eb = ebuf + ((size_t)bh * SEQ + i0) * SEQ;
    float* Ab = attn + ((size_t)bh * SEQ + i0) * SEQ;
    const __half* Vbh = vhi + (size_t)bh * SEQ * HD;
    const __half* Vbl = vlo + (size_t)bh * SEQ * HD;

    wmma::fragment<wmma::accumulator, 16, 16, 16, float> acc[2][2];
#pragma unroll
    for (int i = 0; i < 2; i++)
#pragma unroll
        for (int j = 0; j < 2; j++) wmma::fill_fragment(acc[i][j], 0.f);

    for (int k0 = 0; k0 < SEQ; k0 += 64) {
#pragma unroll
        for (int t = 0; t < 2; t++) {
            int slot = tid + t * 256;
            int row  = slot >> 3;
            int co   = (slot & 7) * 8;
            cp16(sVhi + row * LDK + co, Vbh + (size_t)(k0 + row) * HD + co);
            cp16(sVlo + row * LDK + co, Vbl + (size_t)(k0 + row) * HD + co);
        }
        cp_commit();

#pragma unroll
        for (int t = 0; t < 4; t++) {
            int slot = tid + t * 256;
            int row  = slot >> 3;
            int c8   = (slot & 7) * 8;
            float iz = invZ[row];
            uint4 raw = *(const uint4*)&Eb[(size_t)row * SEQ + k0 + c8];
            *(uint4*)&sP[row * LDK + c8] = raw;
            float2 f0 = __half22float2(*(__half2*)&raw.x);
            float2 f1 = __half22float2(*(__half2*)&raw.y);
            float2 f2 = __half22float2(*(__half2*)&raw.z);
            float2 f3 = __half22float2(*(__half2*)&raw.w);
            *(float4*)&Ab[(size_t)row * SEQ + k0 + c8] =
                make_float4(f0.x*iz, f0.y*iz, f1.x*iz, f1.y*iz);
            *(float4*)&Ab[(size_t)row * SEQ + k0 + c8 + 4] =
                make_float4(f2.x*iz, f2.y*iz, f3.x*iz, f3.y*iz);
        }
        asm volatile("cp.async.wait_group 0;");
        __syncthreads();

#pragma unroll
        for (int kk = 0; kk < 64; kk += 16) {
            wmma::fragment<wmma::matrix_a, 16, 16, 16, __half, wmma::row_major> aP[2];
            wmma::fragment<wmma::matrix_b, 16, 16, 16, __half, wmma::row_major> bHi[2], bLo[2];
#pragma unroll
            for (int i = 0; i < 2; i++)
                wmma::load_matrix_sync(aP[i], &sP[(wr * 32 + i * 16) * LDK + kk], LDK);
#pragma unroll
            for (int j = 0; j < 2; j++) {
                wmma::load_matrix_sync(bHi[j], &sVhi[kk * LDK + wc * 32 + j * 16], LDK);
                wmma::load_matrix_sync(bLo[j], &sVlo[kk * LDK + wc * 32 + j * 16], LDK);
            }
#pragma unroll
            for (int i = 0; i < 2; i++)
#pragma unroll
                for (int j = 0; j < 2; j++) {
                    wmma::mma_sync(acc[i][j], aP[i], bHi[j], acc[i][j]);
                    wmma::mma_sync(acc[i][j], aP[i], bLo[j], acc[i][j]);
                }
        }
        __syncthreads();
    }

    float* scratch = (float*)smp;
    float* ws = scratch + wid * 16 * 20;
    const int er = lane >> 1;
    const int ec = (lane & 1) * 8;

#pragma unroll
    for (int i = 0; i < 2; i++)
#pragma unroll
        for (int j = 0; j < 2; j++) {
            wmma::store_matrix_sync(ws, acc[i][j], 20, wmma::mem_row_major);
            __syncwarp();
            int rl  = wr * 32 + i * 16 + er;
            int col = wc * 32 + j * 16 + ec;
            float iz = invZ[rl];
            size_t off = ((size_t)b * SEQ + i0 + rl) * DM + h * HD + col;
            float vv[8];
#pragma unroll
            for (int e = 0; e < 8; e++) vv[e] = ws[er * 20 + ec + e] * iz;
            __nv_bfloat16 hh[8];
#pragma unroll
            for (int e = 0; e < 8; e++) hh[e] = __float2bfloat16(vv[e]);
            __nv_bfloat162 p0(hh[0],hh[1]), p1(hh[2],hh[3]), p2(hh[4],hh[5]), p3(hh[6],hh[7]);
            *(uint4*)&ctxhi[off] = make_uint4(*(uint32_t*)&p0, *(uint32_t*)&p1,
                                              *(uint32_t*)&p2, *(uint32_t*)&p3);
            uint4 ul;
            ul.x = bfpack(vv[0]-__bfloat162float(hh[0]), vv[1]-__bfloat162float(hh[1]));
            ul.y = bfpack(vv[2]-__bfloat162float(hh[2]), vv[3]-__bfloat162float(hh[3]));
            ul.z = bfpack(vv[4]-__bfloat162float(hh[4]), vv[5]-__bfloat162float(hh[5]));
            ul.w = bfpack(vv[6]-__bfloat162float(hh[6]), vv[7]-__bfloat162float(hh[7]));
            *(uint4*)&ctxlo[off] = ul;
            __syncwarp();
        }
}

// ---------------------------------------------------------------------------
// Launch
// ---------------------------------------------------------------------------
extern "C" void kernel_launch(void* const* d_in, const int* in_sizes, int n_in,
                              void* d_out, int out_size)
{
    const float* query = (const float*)d_in[0];
    const float* key   = (const float*)d_in[1];
    const float* value = (const float*)d_in[2];
    const float* Wq    = (const float*)d_in[3];
    const float* bq    = (const float*)d_in[4];
    const float* Wk    = (const float*)d_in[5];
    const float* bk    = (const float*)d_in[6];
    const float* Wv    = (const float*)d_in[7];
    const float* bv    = (const float*)d_in[8];
    const float* Wo    = (const float*)d_in[9];
    const float* bo    = (const float*)d_in[10];
    const float* reso  = (const float*)d_in[11];
    const float* phas  = (const float*)d_in[12];

    __nv_bfloat16 *xqh,*xql,*xkh,*xkl,*xvh,*xvl, *wqh,*wql,*wkh,*wkl,*wvh,*wvl,*woh,*wol;
    __nv_bfloat16 *qh,*ql,*kh,*kl, *cxh,*cxl;
    __half *vh,*vl, *eb;
    float *zf, *scratch;
    cudaGetSymbolAddress((void**)&xqh, g_xq_hi); cudaGetSymbolAddress((void**)&xql, g_xq_lo);
    cudaGetSymbolAddress((void**)&xkh, g_xk_hi); cudaGetSymbolAddress((void**)&xkl, g_xk_lo);
    cudaGetSymbolAddress((void**)&xvh, g_xv_hi); cudaGetSymbolAddress((void**)&xvl, g_xv_lo);
    cudaGetSymbolAddress((void**)&wqh, g_wq_hi); cudaGetSymbolAddress((void**)&wql, g_wq_lo);
    cudaGetSymbolAddress((void**)&wkh, g_wk_hi); cudaGetSymbolAddress((void**)&wkl, g_wk_lo);
    cudaGetSymbolAddress((void**)&wvh, g_wv_hi); cudaGetSymbolAddress((void**)&wvl, g_wv_lo);
    cudaGetSymbolAddress((void**)&woh, g_wo_hi); cudaGetSymbolAddress((void**)&wol, g_wo_lo);
    cudaGetSymbolAddress((void**)&qh,  g_q_hi);  cudaGetSymbolAddress((void**)&ql,  g_q_lo);
    cudaGetSymbolAddress((void**)&kh,  g_k_hi);  cudaGetSymbolAddress((void**)&kl,  g_k_lo);
    cudaGetSymbolAddress((void**)&vh,  g_v_hi);  cudaGetSymbolAddress((void**)&vl,  g_v_lo);
    cudaGetSymbolAddress((void**)&cxh, g_ctx_hi); cudaGetSymbolAddress((void**)&cxl, g_ctx_lo);
    cudaGetSymbolAddress((void**)&eb,  g_e);
    cudaGetSymbolAddress((void**)&zf,  g_z);
    cudaGetSymbolAddress((void**)&scratch, g_attn_scratch);

    float* out_ptr = (float*)d_out;
    const bool attn_in_out = ((size_t)out_size >= OUT_ELEMS + ATTN_ELEMS);
    float* attn_ptr = attn_in_out ? (out_ptr + OUT_ELEMS) : scratch;

    const int GEMM_SMEM = 2 * GSTAGE * 2;   // 81920 B
    cudaFuncSetAttribute(gemm_bf16<0>, cudaFuncAttributeMaxDynamicSharedMemorySize, GEMM_SMEM);
    cudaFuncSetAttribute(gemm_bf16<1>, cudaFuncAttributeMaxDynamicSharedMemorySize, GEMM_SMEM);
    cudaFuncSetAttribute(scores_strip, cudaFuncAttributeMaxDynamicSharedMemorySize, SC_SMEM);
    cudaFuncSetAttribute(pv_wmma,      cudaFuncAttributeMaxDynamicSharedMemorySize, PV_SMEM);

    // 0) batched split fp32 -> bf16 hi/lo (one launch)
    const int NX4 = MTOT * DM / 4, NW4 = DM * DM / 4;
    ConvPtrs C = {};
    C.src[0]=(const float4*)query; C.hi[0]=(uint2*)xqh; C.lo[0]=(uint2*)xql; C.n4[0]=NX4;
    C.src[1]=(const float4*)key;   C.hi[1]=(uint2*)xkh; C.lo[1]=(uint2*)xkl; C.n4[1]=NX4;
    C.src[2]=(const float4*)value; C.hi[2]=(uint2*)xvh; C.lo[2]=(uint2*)xvl; C.n4[2]=NX4;
    C.src[3]=(const float4*)Wq;    C.hi[3]=(uint2*)wqh; C.lo[3]=(uint2*)wql; C.n4[3]=NW4;
    C.src[4]=(const float4*)Wk;    C.hi[4]=(uint2*)wkh; C.lo[4]=(uint2*)wkl; C.n4[4]=NW4;
    C.src[5]=(const float4*)Wv;    C.hi[5]=(uint2*)wvh; C.lo[5]=(uint2*)wvl; C.n4[5]=NW4;
    C.src[6]=(const float4*)Wo;    C.hi[6]=(uint2*)woh; C.lo[6]=(uint2*)wol; C.n4[6]=NW4;
    dim3 gC((NX4 + 255) / 256, 1, 7);
    convert_split_b<<<gC, 256>>>(C);

    // 1) QKV projections (q,k bf16 hi/lo; v fp16 hi/lo)
    GemmPtrs Pq = {};
    Pq.Ahi[0]=xqh; Pq.Alo[0]=xql; Pq.Whi[0]=wqh; Pq.Wlo[0]=wql; Pq.bias[0]=bq;
    Pq.outHi[0]=qh; Pq.outLo[0]=ql; Pq.f16[0]=0;
    Pq.Ahi[1]=xkh; Pq.Alo[1]=xkl; Pq.Whi[1]=wkh; Pq.Wlo[1]=wkl; Pq.bias[1]=bk;
    Pq.outHi[1]=kh; Pq.outLo[1]=kl; Pq.f16[1]=0;
    Pq.Ahi[2]=xvh; Pq.Alo[2]=xvl; Pq.Whi[2]=wvh; Pq.Wlo[2]=wvl; Pq.bias[2]=bv;
    Pq.outHi[2]=vh; Pq.outLo[2]=vl; Pq.f16[2]=1;
    dim3 gP(DM / 128, MTOT / 128, 3);
    gemm_bf16<0><<<gP, 256, GEMM_SMEM>>>(Pq, MTOT, DM, DM);

    // 2) Scores strip-persistent -> fp16 e + full Z
    dim3 gS(SEQ / 128, BATCH * NH);
    scores_strip<<<gS, 256, SC_SMEM>>>(qh, ql, kh, kl, reso, phas, eb, zf);

    // 3) PV fp16: attn out + e@V -> ctx hi/lo
    dim3 gV(SEQ / 128, BATCH * NH);
    pv_wmma<<<gV, 256, PV_SMEM>>>(eb, attn_ptr, vh, vl, zf, cxh, cxl);

    // 4) Output projection -> d_out
    GemmPtrs Po = {};
    Po.Ahi[0]=cxh; Po.Alo[0]=cxl; Po.Whi[0]=woh; Po.Wlo[0]=wol; Po.bias[0]=bo;
    Po.outF[0]=out_ptr;
    dim3 gO(DM / 128, MTOT / 128, 1);
    gemm_bf16<1><<<gO, 256, GEMM_SMEM>>>(Po, MTOT, DM, DM);
}

// round 16
// speedup vs baseline: 1.2355x; 1.0901x over previous
#include <cuda_runtime.h>
#include <cuda_bf16.h>
#include <cuda_fp16.h>
#include <mma.h>
#include <math.h>
#include <stdint.h>

using namespace nvcuda;

#define BATCH 2
#define SEQ   2048
#define DM    1024
#define NH    16
#define HD    64
#define MTOT  (BATCH*SEQ)
#define JT    (SEQ/128)
#define LDK   72
#define STG_LD 136

static const size_t OUT_ELEMS  = (size_t)BATCH * SEQ * DM;
static const size_t ATTN_ELEMS = (size_t)BATCH * NH * SEQ * SEQ;

// ---------------------------------------------------------------------------
// Device scratch
// ---------------------------------------------------------------------------
__device__ __nv_bfloat16 g_xq_hi[MTOT*DM], g_xq_lo[MTOT*DM];
__device__ __nv_bfloat16 g_xk_hi[MTOT*DM], g_xk_lo[MTOT*DM];
__device__ __nv_bfloat16 g_xv_hi[MTOT*DM], g_xv_lo[MTOT*DM];
__device__ __nv_bfloat16 g_wq_hi[DM*DM], g_wq_lo[DM*DM];
__device__ __nv_bfloat16 g_wk_hi[DM*DM], g_wk_lo[DM*DM];
__device__ __nv_bfloat16 g_wv_hi[DM*DM], g_wv_lo[DM*DM];
__device__ __nv_bfloat16 g_wo_hi[DM*DM], g_wo_lo[DM*DM];
__device__ __nv_bfloat16 g_q_hi[BATCH*NH*SEQ*HD], g_q_lo[BATCH*NH*SEQ*HD];
__device__ __nv_bfloat16 g_k_hi[BATCH*NH*SEQ*HD], g_k_lo[BATCH*NH*SEQ*HD];
__device__ __half        g_v_hi[BATCH*NH*SEQ*HD], g_v_lo[BATCH*NH*SEQ*HD];
__device__ __nv_bfloat16 g_ctx_hi[MTOT*DM], g_ctx_lo[MTOT*DM];
__device__ __half g_e[(size_t)BATCH*NH*SEQ*SEQ];
__device__ float g_z[(size_t)BATCH*NH*SEQ];
__device__ float g_attn_scratch[(size_t)BATCH*NH*SEQ*SEQ];

// ---------------------------------------------------------------------------
// Helpers
// ---------------------------------------------------------------------------
__device__ __forceinline__ void cp16(void* dst, const void* src) {
    asm volatile("cp.async.cg.shared.global [%0], [%1], 16;"
                 :: "r"((uint32_t)__cvta_generic_to_shared(dst)), "l"(src));
}
__device__ __forceinline__ void cp_commit() {
    asm volatile("cp.async.commit_group;");
}
__device__ __forceinline__ uint32_t bfpack(float a, float b) {
    __nv_bfloat162 t(__float2bfloat16(a), __float2bfloat16(b));
    return *(uint32_t*)&t;
}
__device__ __forceinline__ uint32_t hfpack(float a, float b) {
    __half2 t(__float2half_rn(a), __float2half_rn(b));
    return *(uint32_t*)&t;
}

// batched fp32 -> bf16 hi/lo split: grid.z selects tensor
struct ConvPtrs { const float4* src[7]; uint2* hi[7]; uint2* lo[7]; int n4[7]; };

__global__ void __launch_bounds__(256)
convert_split_b(ConvPtrs C)
{
    int z = blockIdx.z;
    int i = blockIdx.x * 256 + threadIdx.x;
    if (i >= C.n4[z]) return;
    float4 v = C.src[z][i];
    __nv_bfloat16 hx = __float2bfloat16(v.x), hy = __float2bfloat16(v.y);
    __nv_bfloat16 hz = __float2bfloat16(v.z), hw = __float2bfloat16(v.w);
    __nv_bfloat162 h01(hx, hy), h23(hz, hw);
    C.hi[z][i] = make_uint2(*(uint32_t*)&h01, *(uint32_t*)&h23);
    C.lo[z][i] = make_uint2(bfpack(v.x - __bfloat162float(hx), v.y - __bfloat162float(hy)),
                            bfpack(v.z - __bfloat162float(hz), v.w - __bfloat162float(hw)));
}

// ---------------------------------------------------------------------------
// HMMA GEMM, KC=32 chunks, 2 CTAs/SM (R15-proven)
// ---------------------------------------------------------------------------
struct GemmPtrs {
    const __nv_bfloat16 *Ahi[3], *Alo[3], *Whi[3], *Wlo[3];
    const float* bias[3];
    float* outF[3];
    void *outHi[3], *outLo[3];
    int f16[3];
};

#define KCG 32
#define LDG2 40
#define GTILE (128*LDG2)
#define GSTAGE (4*GTILE)

template<int MODE>
__global__ void __launch_bounds__(256, 2)
gemm_bf16(GemmPtrs P, int M, int N, int K)
{
    extern __shared__ __align__(16) __nv_bfloat16 sm[];
    const int z = (MODE == 0) ? blockIdx.z : 0;
    const __nv_bfloat16* Ahi = P.Ahi[z];
    const __nv_bfloat16* Alo = P.Alo[z];
    const __nv_bfloat16* Whi = P.Whi[z];
    const __nv_bfloat16* Wlo = P.Wlo[z];
    const float* bias = P.bias[z];

    const int tid = threadIdx.x;
    const int wid = tid >> 5;
    const int lane = tid & 31;
    const int wr = wid & 3;
    const int wc = wid >> 2;
    const int m0 = blockIdx.y * 128;
    const int n0 = blockIdx.x * 128;

    wmma::fragment<wmma::accumulator, 16, 16, 16, float> acc[2][4];
#pragma unroll
    for (int i = 0; i < 2; i++)
#pragma unroll
        for (int j = 0; j < 4; j++) wmma::fill_fragment(acc[i][j], 0.f);

    const int NC = K / KCG;

    auto stage_copy = [&](int c, int s) {
        const int k0 = c * KCG;
        __nv_bfloat16* base = sm + s * GSTAGE;
#pragma unroll
        for (int t = 0; t < 2; t++) {
            int slot = tid + t * 256;
            int row  = slot >> 2;
            int coff = (slot & 3) * 8;
            cp16(base + 0*GTILE + row * LDG2 + coff, Ahi + (size_t)(m0 + row) * K + k0 + coff);
            cp16(base + 1*GTILE + row * LDG2 + coff, Alo + (size_t)(m0 + row) * K + k0 + coff);
            cp16(base + 2*GTILE + row * LDG2 + coff, Whi + (size_t)(n0 + row) * K + k0 + coff);
            cp16(base + 3*GTILE + row * LDG2 + coff, Wlo + (size_t)(n0 + row) * K + k0 + coff);
        }
        cp_commit();
    };

    stage_copy(0, 0);

    for (int c = 0; c < NC; c++) {
        if (c + 1 < NC) stage_copy(c + 1, (c + 1) & 1);
        if (c + 1 < NC) asm volatile("cp.async.wait_group 1;");
        else            asm volatile("cp.async.wait_group 0;");
        __syncthreads();

        const __nv_bfloat16* base = sm + (c & 1) * GSTAGE;
        const __nv_bfloat16* sAhi = base + 0*GTILE;
        const __nv_bfloat16* sAlo = base + 1*GTILE;
        const __nv_bfloat16* sWhi = base + 2*GTILE;
        const __nv_bfloat16* sWlo = base + 3*GTILE;

#pragma unroll
        for (int kk = 0; kk < KCG; kk += 16) {
            wmma::fragment<wmma::matrix_a, 16, 16, 16, __nv_bfloat16, wmma::row_major> aHi[2], aLo[2];
            wmma::fragment<wmma::matrix_b, 16, 16, 16, __nv_bfloat16, wmma::col_major> bHi[4], bLo[4];
#pragma unroll
            for (int i = 0; i < 2; i++) {
                wmma::load_matrix_sync(aHi[i], &sAhi[(wr * 32 + i * 16) * LDG2 + kk], LDG2);
                wmma::load_matrix_sync(aLo[i], &sAlo[(wr * 32 + i * 16) * LDG2 + kk], LDG2);
            }
#pragma unroll
            for (int j = 0; j < 4; j++) {
                wmma::load_matrix_sync(bHi[j], &sWhi[(wc * 64 + j * 16) * LDG2 + kk], LDG2);
                wmma::load_matrix_sync(bLo[j], &sWlo[(wc * 64 + j * 16) * LDG2 + kk], LDG2);
            }
#pragma unroll
            for (int i = 0; i < 2; i++)
#pragma unroll
                for (int j = 0; j < 4; j++) {
                    wmma::mma_sync(acc[i][j], aHi[i], bHi[j], acc[i][j]);
                    wmma::mma_sync(acc[i][j], aHi[i], bLo[j], acc[i][j]);
                    wmma::mma_sync(acc[i][j], aLo[i], bHi[j], acc[i][j]);
                }
        }
        __syncthreads();
    }

    float* scratch = (float*)sm;
    float* ws = scratch + wid * 16 * 20;
    const int er = lane >> 1;
    const int ec = (lane & 1) * 8;

#pragma unroll
    for (int i = 0; i < 2; i++)
#pragma unroll
        for (int j = 0; j < 4; j++) {
            wmma::store_matrix_sync(ws, acc[i][j], 20, wmma::mem_row_major);
            __syncwarp();
            int grow = m0 + wr * 32 + i * 16 + er;
            int col  = n0 + wc * 64 + j * 16 + ec;
            float4 b0 = *(const float4*)&bias[col];
            float4 b1 = *(const float4*)&bias[col + 4];
            float vv[8];
#pragma unroll
            for (int e = 0; e < 4; e++) vv[e]     = ws[er * 20 + ec + e]     + (&b0.x)[e];
#pragma unroll
            for (int e = 0; e < 4; e++) vv[e + 4] = ws[er * 20 + ec + 4 + e] + (&b1.x)[e];

            if (MODE == 0) {
                int b  = grow >> 11;
                int s  = grow & (SEQ - 1);
                int hh = col >> 6;
                int dd = col & (HD - 1);
                size_t off = (((size_t)(b * NH + hh)) * SEQ + s) * HD + dd;
                if (P.f16[z]) {
                    __half h[8];
#pragma unroll
                    for (int e = 0; e < 8; e++) h[e] = __float2half_rn(vv[e]);
                    __half2 p0(h[0],h[1]), p1(h[2],h[3]), p2(h[4],h[5]), p3(h[6],h[7]);
                    uint4 uh = make_uint4(*(uint32_t*)&p0, *(uint32_t*)&p1,
                                          *(uint32_t*)&p2, *(uint32_t*)&p3);
                    uint4 ul;
                    ul.x = hfpack(vv[0]-__half2float(h[0]), vv[1]-__half2float(h[1]));
                    ul.y = hfpack(vv[2]-__half2float(h[2]), vv[3]-__half2float(h[3]));
                    ul.z = hfpack(vv[4]-__half2float(h[4]), vv[5]-__half2float(h[5]));
                    ul.w = hfpack(vv[6]-__half2float(h[6]), vv[7]-__half2float(h[7]));
                    *(uint4*)&((__half*)P.outHi[z])[off] = uh;
                    *(uint4*)&((__half*)P.outLo[z])[off] = ul;
                } else {
                    uint4 uh, ul;
                    __nv_bfloat16 h[8];
#pragma unroll
                    for (int e = 0; e < 8; e++) h[e] = __float2bfloat16(vv[e]);
                    __nv_bfloat162 p0(h[0],h[1]), p1(h[2],h[3]), p2(h[4],h[5]), p3(h[6],h[7]);
                    uh = make_uint4(*(uint32_t*)&p0, *(uint32_t*)&p1, *(uint32_t*)&p2, *(uint32_t*)&p3);
                    ul.x = bfpack(vv[0]-__bfloat162float(h[0]), vv[1]-__bfloat162float(h[1]));
                    ul.y = bfpack(vv[2]-__bfloat162float(h[2]), vv[3]-__bfloat162float(h[3]));
                    ul.z = bfpack(vv[4]-__bfloat162float(h[4]), vv[5]-__bfloat162float(h[5]));
                    ul.w = bfpack(vv[6]-__bfloat162float(h[6]), vv[7]-__bfloat162float(h[7]));
                    *(uint4*)&((__nv_bfloat16*)P.outHi[z])[off] = uh;
                    *(uint4*)&((__nv_bfloat16*)P.outLo[z])[off] = ul;
                }
            } else {
                float* dst = &P.outF[0][(size_t)grow * N + col];
                *(float4*)dst       = make_float4(vv[0], vv[1], vv[2], vv[3]);
                *(float4*)(dst + 4) = make_float4(vv[4], vv[5], vv[6], vv[7]);
            }
            __syncwarp();
        }
}

// ---------------------------------------------------------------------------
// Scores, STRIP-PERSISTENT (R12/R15 exact)
// ---------------------------------------------------------------------------
#define SQT (128*LDK)
#define SC_SMEM (6*SQT*2 + 128*STG_LD*4)

__global__ void __launch_bounds__(256)
scores_strip(const __nv_bfloat16* __restrict__ qhi, const __nv_bfloat16* __restrict__ qlo,
             const __nv_bfloat16* __restrict__ khi, const __nv_bfloat16* __restrict__ klo,
             const float* __restrict__ res, const float* __restrict__ ph,
             __half* __restrict__ ebuf, float* __restrict__ zout)
{
    extern __shared__ __align__(16) __nv_bfloat16 smf[];
    __nv_bfloat16* sQhi = smf;
    __nv_bfloat16* sQlo = smf + SQT;
    float* stage = (float*)(smf + 6*SQT);

    const int bh = blockIdx.y;
    const int h  = bh & (NH - 1);
    const int i0 = blockIdx.x * 128;
    const int tid = threadIdx.x;
    const int wid = tid >> 5;
    const int wr = wid & 3;
    const int wc = wid >> 2;

    const size_t hbase = (size_t)bh * SEQ * HD;
    const float R  = res[h];
    const float Pp = ph[h];

#pragma unroll
    for (int t = 0; t < 4; t++) {
        int chunk = tid + t * 256;
        int row  = chunk >> 3;
        int co   = (chunk & 7) * 8;
        cp16(sQhi + row * LDK + co, qhi + hbase + (size_t)(i0 + row) * HD + co);
        cp16(sQlo + row * LDK + co, qlo + hbase + (size_t)(i0 + row) * HD + co);
    }
    cp_commit();

    auto cpK = [&](int jt, int buf) {
        __nv_bfloat16* dKhi = smf + 2*SQT + buf * 2*SQT;
        __nv_bfloat16* dKlo = dKhi + SQT;
        const int j0 = jt * 128;
#pragma unroll
        for (int t = 0; t < 4; t++) {
            int chunk = tid + t * 256;
            int row  = chunk >> 3;
            int co   = (chunk & 7) * 8;
            cp16(dKhi + row * LDK + co, khi + hbase + (size_t)(j0 + row) * HD + co);
            cp16(dKlo + row * LDK + co, klo + hbase + (size_t)(j0 + row) * HD + co);
        }
        cp_commit();
    };

    cpK(0, 0);

    const int row_e = tid >> 1;
    const int c0_e  = (tid & 1) * 64;
    float zsum = 0.f;

    for (int jt = 0; jt < JT; jt++) {
        asm volatile("cp.async.wait_group 0;");
        __syncthreads();
        if (jt + 1 < JT) cpK(jt + 1, (jt + 1) & 1);

        const __nv_bfloat16* sKhi = smf + 2*SQT + (jt & 1) * 2*SQT;
        const __nv_bfloat16* sKlo = sKhi + SQT;

        wmma::fragment<wmma::accumulator, 16, 16, 16, float> acc[2][4];
#pragma unroll
        for (int i = 0; i < 2; i++)
#pragma unroll
            for (int j = 0; j < 4; j++) wmma::fill_fragment(acc[i][j], 0.f);

#pragma unroll
        for (int kk = 0; kk < 64; kk += 16) {
            wmma::fragment<wmma::matrix_a, 16, 16, 16, __nv_bfloat16, wmma::row_major> aHi[2], aLo[2];
            wmma::fragment<wmma::matrix_b, 16, 16, 16, __nv_bfloat16, wmma::col_major> bHi[4], bLo[4];
#pragma unroll
            for (int i = 0; i < 2; i++) {
                wmma::load_matrix_sync(aHi[i], &sQhi[(wr * 32 + i * 16) * LDK + kk], LDK);
                wmma::load_matrix_sync(aLo[i], &sQlo[(wr * 32 + i * 16) * LDK + kk], LDK);
            }
#pragma unroll
            for (int j = 0; j < 4; j++) {
                wmma::load_matrix_sync(bHi[j], &sKhi[(wc * 64 + j * 16) * LDK + kk], LDK);
                wmma::load_matrix_sync(bLo[j], &sKlo[(wc * 64 + j * 16) * LDK + kk], LDK);
            }
#pragma unroll
            for (int i = 0; i < 2; i++)
#pragma unroll
                for (int j = 0; j < 4; j++) {
                    wmma::mma_sync(acc[i][j], aHi[i], bHi[j], acc[i][j]);
                    wmma::mma_sync(acc[i][j], aHi[i], bLo[j], acc[i][j]);
                    wmma::mma_sync(acc[i][j], aLo[i], bHi[j], acc[i][j]);
                }
        }

#pragma unroll
        for (int i = 0; i < 2; i++)
#pragma unroll
            for (int j = 0; j < 4; j++)
#pragma unroll
                for (int e = 0; e < acc[i][j].num_elements; e++) {
                    float s = acc[i][j].x[e] * 0.125f;
                    s += R * __sinf(s + Pp);
                    acc[i][j].x[e] = __expf(s);
                }

#pragma unroll
        for (int i = 0; i < 2; i++)
#pragma unroll
            for (int j = 0; j < 4; j++)
                wmma::store_matrix_sync(&stage[(size_t)(wr * 32 + i * 16) * STG_LD + wc * 64 + j * 16],
                                        acc[i][j], STG_LD, wmma::mem_row_major);
        __syncthreads();

        {
            const float* pr = &stage[(size_t)row_e * STG_LD + c0_e];
            __half* erow = ebuf + ((size_t)bh * SEQ + i0 + row_e) * SEQ + jt * 128 + c0_e;
#pragma unroll
            for (int c = 0; c < 64; c += 8) {
                float4 v0 = *(const float4*)&pr[c];
                float4 v1 = *(const float4*)&pr[c + 4];
                zsum += v0.x + v0.y + v0.z + v0.w + v1.x + v1.y + v1.z + v1.w;
                __half2 e0 = __floats2half2_rn(v0.x, v0.y);
                __half2 e1 = __floats2half2_rn(v0.z, v0.w);
                __half2 e2 = __floats2half2_rn(v1.x, v1.y);
                __half2 e3 = __floats2half2_rn(v1.z, v1.w);
                *(uint4*)&erow[c] = make_uint4(*(uint32_t*)&e0, *(uint32_t*)&e1,
                                               *(uint32_t*)&e2, *(uint32_t*)&e3);
            }
        }
    }

    zsum += __shfl_xor_sync(0xffffffffu, zsum, 1);
    if ((tid & 1) == 0)
        zout[(size_t)bh * SEQ + i0 + row_e] = zsum;
}

// ---------------------------------------------------------------------------
// PV on fp16 HMMA, with register-prefetched e and streaming attn stores.
// ---------------------------------------------------------------------------
#define PT16 (128*LDK)
#define VT16 (64*LDK)
#define PV_SMEM ((PT16 + 2*VT16) * 2)

__global__ void __launch_bounds__(256)
pv_wmma(const __half* __restrict__ ebuf, float* __restrict__ attn,
        const __half* __restrict__ vhi, const __half* __restrict__ vlo,
        const float* __restrict__ zfull,
        __nv_bfloat16* __restrict__ ctxhi, __nv_bfloat16* __restrict__ ctxlo)
{
    extern __shared__ __align__(16) __half smp[];
    __half* sP   = smp;
    __half* sVhi = smp + PT16;
    __half* sVlo = smp + PT16 + VT16;
    __shared__ float invZ[128];

    const int bh = blockIdx.y;
    const int b  = bh >> 4;
    const int h  = bh & 15;
    const int i0 = blockIdx.x * 128;
    const int tid = threadIdx.x;
    const int wid = tid >> 5;
    const int lane = tid & 31;
    const int wr = wid & 3;
    const int wc = wid >> 2;

    if (tid < 128)
        invZ[tid] = 1.f / zfull[(size_t)bh * SEQ + i0 + tid];
    __syncthreads();

    const __half* Eb = ebuf + ((size_t)bh * SEQ + i0) * SEQ;
    float* Ab = attn + ((size_t)bh * SEQ + i0) * SEQ;
    const __half* Vbh = vhi + (size_t)bh * SEQ * HD;
    const __half* Vbl = vlo + (size_t)bh * SEQ * HD;

    // e address pattern: per pass t, row = row0 + 32t, col byte group fixed
    const int row0 = tid >> 3;            // 0..31
    const int c8   = (tid & 7) * 8;       // 0..56

    wmma::fragment<wmma::accumulator, 16, 16, 16, float> acc[2][2];
#pragma unroll
    for (int i = 0; i < 2; i++)
#pragma unroll
        for (int j = 0; j < 2; j++) wmma::fill_fragment(acc[i][j], 0.f);

    const int NC = SEQ / 64;

    // prefetch chunk 0 e into registers
    uint4 ereg[4];
#pragma unroll
    for (int t = 0; t < 4; t++)
        ereg[t] = *(const uint4*)&Eb[(size_t)(row0 + 32 * t) * SEQ + 0 + c8];

    for (int c = 0; c < NC; c++) {
        const int k0 = c * 64;
        // V tiles via cp.async
#pragma unroll
        for (int t = 0; t < 2; t++) {
            int slot = tid + t * 256;
            int row  = slot >> 3;
            int co   = (slot & 7) * 8;
            cp16(sVhi + row * LDK + co, Vbh + (size_t)(k0 + row) * HD + co);
            cp16(sVlo + row * LDK + co, Vbl + (size_t)(k0 + row) * HD + co);
        }
        cp_commit();

        // store prefetched e regs: smem P tile + streaming attn write
#pragma unroll
        for (int t = 0; t < 4; t++) {
            int row = row0 + 32 * t;
            float iz = invZ[row];
            uint4 raw = ereg[t];
            *(uint4*)&sP[row * LDK + c8] = raw;
            float2 f0 = __half22float2(*(__half2*)&raw.x);
            float2 f1 = __half22float2(*(__half2*)&raw.y);
            float2 f2 = __half22float2(*(__half2*)&raw.z);
            float2 f3 = __half22float2(*(__half2*)&raw.w);
            __stcs((float4*)&Ab[(size_t)row * SEQ + k0 + c8],
                   make_float4(f0.x*iz, f0.y*iz, f1.x*iz, f1.y*iz));
            __stcs((float4*)&Ab[(size_t)row * SEQ + k0 + c8 + 4],
                   make_float4(f2.x*iz, f2.y*iz, f3.x*iz, f3.y*iz));
        }

        // issue next chunk's e loads NOW (latency hidden under MMA below)
        if (c + 1 < NC) {
            const int kn = (c + 1) * 64;
#pragma unroll
            for (int t = 0; t < 4; t++)
                ereg[t] = *(const uint4*)&Eb[(size_t)(row0 + 32 * t) * SEQ + kn + c8];
        }

        asm volatile("cp.async.wait_group 0;");
        __syncthreads();

#pragma unroll
        for (int kk = 0; kk < 64; kk += 16) {
            wmma::fragment<wmma::matrix_a, 16, 16, 16, __half, wmma::row_major> aP[2];
            wmma::fragment<wmma::matrix_b, 16, 16, 16, __half, wmma::row_major> bHi[2], bLo[2];
#pragma unroll
            for (int i = 0; i < 2; i++)
                wmma::load_matrix_sync(aP[i], &sP[(wr * 32 + i * 16) * LDK + kk], LDK);
#pragma unroll
            for (int j = 0; j < 2; j++) {
                wmma::load_matrix_sync(bHi[j], &sVhi[kk * LDK + wc * 32 + j * 16], LDK);
                wmma::load_matrix_sync(bLo[j], &sVlo[kk * LDK + wc * 32 + j * 16], LDK);
            }
#pragma unroll
            for (int i = 0; i < 2; i++)
#pragma unroll
                for (int j = 0; j < 2; j++) {
                    wmma::mma_sync(acc[i][j], aP[i], bHi[j], acc[i][j]);
                    wmma::mma_sync(acc[i][j], aP[i], bLo[j], acc[i][j]);
                }
        }
        __syncthreads();
    }

    float* scratch = (float*)smp;
    float* ws = scratch + wid * 16 * 20;
    const int er = lane >> 1;
    const int ec = (lane & 1) * 8;

#pragma unroll
    for (int i = 0; i < 2; i++)
#pragma unroll
        for (int j = 0; j < 2; j++) {
            wmma::store_matrix_sync(ws, acc[i][j], 20, wmma::mem_row_major);
            __syncwarp();
            int rl  = wr * 32 + i * 16 + er;
            int col = wc * 32 + j * 16 + ec;
            float iz = invZ[rl];
            size_t off = ((size_t)b * SEQ + i0 + rl) * DM + h * HD + col;
            float vv[8];
#pragma unroll
            for (int e = 0; e < 8; e++) vv[e] = ws[er * 20 + ec + e] * iz;
            __nv_bfloat16 hh[8];
#pragma unroll
            for (int e = 0; e < 8; e++) hh[e] = __float2bfloat16(vv[e]);
            __nv_bfloat162 p0(hh[0],hh[1]), p1(hh[2],hh[3]), p2(hh[4],hh[5]), p3(hh[6],hh[7]);
            *(uint4*)&ctxhi[off] = make_uint4(*(uint32_t*)&p0, *(uint32_t*)&p1,
                                              *(uint32_t*)&p2, *(uint32_t*)&p3);
            uint4 ul;
            ul.x = bfpack(vv[0]-__bfloat162float(hh[0]), vv[1]-__bfloat162float(hh[1]));
            ul.y = bfpack(vv[2]-__bfloat162float(hh[2]), vv[3]-__bfloat162float(hh[3]));
            ul.z = bfpack(vv[4]-__bfloat162float(hh[4]), vv[5]-__bfloat162float(hh[5]));
            ul.w = bfpack(vv[6]-__bfloat162float(hh[6]), vv[7]-__bfloat162float(hh[7]));
            *(uint4*)&ctxlo[off] = ul;
            __syncwarp();
        }
}

// ---------------------------------------------------------------------------
// Launch
// ---------------------------------------------------------------------------
extern "C" void kernel_launch(void* const* d_in, const int* in_sizes, int n_in,
                              void* d_out, int out_size)
{
    const float* query = (const float*)d_in[0];
    const float* key   = (const float*)d_in[1];
    const float* value = (const float*)d_in[2];
    const float* Wq    = (const float*)d_in[3];
    const float* bq    = (const float*)d_in[4];
    const float* Wk    = (const float*)d_in[5];
    const float* bk    = (const float*)d_in[6];
    const float* Wv    = (const float*)d_in[7];
    const float* bv    = (const float*)d_in[8];
    const float* Wo    = (const float*)d_in[9];
    const float* bo    = (const float*)d_in[10];
    const float* reso  = (const float*)d_in[11];
    const float* phas  = (const float*)d_in[12];

    __nv_bfloat16 *xqh,*xql,*xkh,*xkl,*xvh,*xvl, *wqh,*wql,*wkh,*wkl,*wvh,*wvl,*woh,*wol;
    __nv_bfloat16 *qh,*ql,*kh,*kl, *cxh,*cxl;
    __half *vh,*vl, *eb;
    float *zf, *scratch;
    cudaGetSymbolAddress((void**)&xqh, g_xq_hi); cudaGetSymbolAddress((void**)&xql, g_xq_lo);
    cudaGetSymbolAddress((void**)&xkh, g_xk_hi); cudaGetSymbolAddress((void**)&xkl, g_xk_lo);
    cudaGetSymbolAddress((void**)&xvh, g_xv_hi); cudaGetSymbolAddress((void**)&xvl, g_xv_lo);
    cudaGetSymbolAddress((void**)&wqh, g_wq_hi); cudaGetSymbolAddress((void**)&wql, g_wq_lo);
    cudaGetSymbolAddress((void**)&wkh, g_wk_hi); cudaGetSymbolAddress((void**)&wkl, g_wk_lo);
    cudaGetSymbolAddress((void**)&wvh, g_wv_hi); cudaGetSymbolAddress((void**)&wvl, g_wv_lo);
    cudaGetSymbolAddress((void**)&woh, g_wo_hi); cudaGetSymbolAddress((void**)&wol, g_wo_lo);
    cudaGetSymbolAddress((void**)&qh,  g_q_hi);  cudaGetSymbolAddress((void**)&ql,  g_q_lo);
    cudaGetSymbolAddress((void**)&kh,  g_k_hi);  cudaGetSymbolAddress((void**)&kl,  g_k_lo);
    cudaGetSymbolAddress((void**)&vh,  g_v_hi);  cudaGetSymbolAddress((void**)&vl,  g_v_lo);
    cudaGetSymbolAddress((void**)&cxh, g_ctx_hi); cudaGetSymbolAddress((void**)&cxl, g_ctx_lo);
    cudaGetSymbolAddress((void**)&eb,  g_e);
    cudaGetSymbolAddress((void**)&zf,  g_z);
    cudaGetSymbolAddress((void**)&scratch, g_attn_scratch);

    float* out_ptr = (float*)d_out;
    const bool attn_in_out = ((size_t)out_size >= OUT_ELEMS + ATTN_ELEMS);
    float* attn_ptr = attn_in_out ? (out_ptr + OUT_ELEMS) : scratch;

    const int GEMM_SMEM = 2 * GSTAGE * 2;
    cudaFuncSetAttribute(gemm_bf16<0>, cudaFuncAttributeMaxDynamicSharedMemorySize, GEMM_SMEM);
    cudaFuncSetAttribute(gemm_bf16<1>, cudaFuncAttributeMaxDynamicSharedMemorySize, GEMM_SMEM);
    cudaFuncSetAttribute(scores_strip, cudaFuncAttributeMaxDynamicSharedMemorySize, SC_SMEM);
    cudaFuncSetAttribute(pv_wmma,      cudaFuncAttributeMaxDynamicSharedMemorySize, PV_SMEM);

    // 0) batched split fp32 -> bf16 hi/lo (one launch)
    const int NX4 = MTOT * DM / 4, NW4 = DM * DM / 4;
    ConvPtrs C = {};
    C.src[0]=(const float4*)query; C.hi[0]=(uint2*)xqh; C.lo[0]=(uint2*)xql; C.n4[0]=NX4;
    C.src[1]=(const float4*)key;   C.hi[1]=(uint2*)xkh; C.lo[1]=(uint2*)xkl; C.n4[1]=NX4;
    C.src[2]=(const float4*)value; C.hi[2]=(uint2*)xvh; C.lo[2]=(uint2*)xvl; C.n4[2]=NX4;
    C.src[3]=(const float4*)Wq;    C.hi[3]=(uint2*)wqh; C.lo[3]=(uint2*)wql; C.n4[3]=NW4;
    C.src[4]=(const float4*)Wk;    C.hi[4]=(uint2*)wkh; C.lo[4]=(uint2*)wkl; C.n4[4]=NW4;
    C.src[5]=(const float4*)Wv;    C.hi[5]=(uint2*)wvh; C.lo[5]=(uint2*)wvl; C.n4[5]=NW4;
    C.src[6]=(const float4*)Wo;    C.hi[6]=(uint2*)woh; C.lo[6]=(uint2*)wol; C.n4[6]=NW4;
    dim3 gC((NX4 + 255) / 256, 1, 7);
    convert_split_b<<<gC, 256>>>(C);

    // 1) QKV projections (q,k bf16 hi/lo; v fp16 hi/lo)
    GemmPtrs Pq = {};
    Pq.Ahi[0]=xqh; Pq.Alo[0]=xql; Pq.Whi[0]=wqh; Pq.Wlo[0]=wql; Pq.bias[0]=bq;
    Pq.outHi[0]=qh; Pq.outLo[0]=ql; Pq.f16[0]=0;
    Pq.Ahi[1]=xkh; Pq.Alo[1]=xkl; Pq.Whi[1]=wkh; Pq.Wlo[1]=wkl; Pq.bias[1]=bk;
    Pq.outHi[1]=kh; Pq.outLo[1]=kl; Pq.f16[1]=0;
    Pq.Ahi[2]=xvh; Pq.Alo[2]=xvl; Pq.Whi[2]=wvh; Pq.Wlo[2]=wvl; Pq.bias[2]=bv;
    Pq.outHi[2]=vh; Pq.outLo[2]=vl; Pq.f16[2]=1;
    dim3 gP(DM / 128, MTOT / 128, 3);
    gemm_bf16<0><<<gP, 256, GEMM_SMEM>>>(Pq, MTOT, DM, DM);

    // 2) Scores strip-persistent -> fp16 e + full Z
    dim3 gS(SEQ / 128, BATCH * NH);
    scores_strip<<<gS, 256, SC_SMEM>>>(qh, ql, kh, kl, reso, phas, eb, zf);

    // 3) PV fp16 (register-prefetched e): attn out + e@V -> ctx hi/lo
    dim3 gV(SEQ / 128, BATCH * NH);
    pv_wmma<<<gV, 256, PV_SMEM>>>(eb, attn_ptr, vh, vl, zf, cxh, cxl);

    // 4) Output projection -> d_out
    GemmPtrs Po = {};
    Po.Ahi[0]=cxh; Po.Alo[0]=cxl; Po.Whi[0]=woh; Po.Wlo[0]=wol; Po.bias[0]=bo;
    Po.outF[0]=out_ptr;
    dim3 gO(DM / 128, MTOT / 128, 1);
    gemm_bf16<1><<<gO, 256, GEMM_SMEM>>>(Po, MTOT, DM, DM);
}